// round 6
// baseline (speedup 1.0000x reference)
#include <cuda_runtime.h>
#include <cuda_bf16.h>
#include <cstdint>
#include <cstddef>

// ---------------- problem constants ----------------
#define NUM_K 512
#define DIM   64
#define T_LEN 8192
#define B_LEN 32

#define MT    128                      // vectors per CTA
#define NTH   256
#define NCTA  ((B_LEN * T_LEN) / MT)   // 2048
#define CAND_W 8.0e-3f                 // capture window (>= 2*eps = 3.2e-3)
#define CAP    20                      // candidate queue per row

// bf16 tiles padded to 72 halfs/row (36 words: +4-bank stagger per row
// -> conflict-free quad-fragment LDS)
#define BP 72
#define W32 36

// Output layout: [quantized B*D*T][loss 1][indices as float B*T]
#define LOSS_OFF ((size_t)B_LEN * DIM * T_LEN)
#define IDX_OFF  (LOSS_OFF + 1)

// ---------------- smem layout (bytes) ----------------
#define SM_X     0                     // fp32 [64][128]                32768
#define SM_A     32768                 // bf16 [128][72]                18432
#define SM_B     51200                 // bf16 [512][72]                73728
#define SM_SEE   124928                // fp32 [512]                     2048
#define SM_XXS   126976                // fp32 [128]                      512
#define SM_SIDX  127488                // int  [128]                      512
#define SM_CAND  128000                // u16  [128][CAP]                5120
#define SM_CNT   133120                // int  [128]                      512
#define SM_REDW  133632                // fp32 [8]                         32
#define SMEM_BYTES 133664

__device__ double g_partial[NCTA];

__device__ __forceinline__ void mma16816(float& d0, float& d1, float& d2, float& d3,
                                         uint32_t a0, uint32_t a1, uint32_t a2,
                                         uint32_t a3, uint32_t b0, uint32_t b1) {
    asm volatile(
        "mma.sync.aligned.m16n8k16.row.col.f32.bf16.bf16.f32 "
        "{%0,%1,%2,%3}, {%4,%5,%6,%7}, {%8,%9}, {%0,%1,%2,%3};"
        : "+f"(d0), "+f"(d1), "+f"(d2), "+f"(d3)
        : "r"(a0), "r"(a1), "r"(a2), "r"(a3), "r"(b0), "r"(b1));
}

// ---------------------------------------------------------------------------
__global__ void __launch_bounds__(NTH, 1)
vq_main(const float* __restrict__ inp, const float* __restrict__ emb,
        float* __restrict__ out) {
    extern __shared__ char smem[];
    float*     X     = (float*)(smem + SM_X);
    float*     see   = (float*)(smem + SM_SEE);
    float*     xxs   = (float*)(smem + SM_XXS);
    int*       sidx  = (int*)(smem + SM_SIDX);
    uint16_t*  scand = (uint16_t*)(smem + SM_CAND);
    int*       scnt  = (int*)(smem + SM_CNT);
    float*     redw  = (float*)(smem + SM_REDW);
    __nv_bfloat162* A2 = (__nv_bfloat162*)(smem + SM_A);
    uint2*     B64   = (uint2*)(smem + SM_B);

    const int tid  = threadIdx.x;
    const int wid  = tid >> 5;
    const int lane = tid & 31;

    const int b  = blockIdx.x >> 6;            // 64 tiles of 128 per batch
    const int t0 = (blockIdx.x & 63) * MT;
    const float* xbase = inp + (size_t)b * DIM * T_LEN + t0;

    if (tid < MT) scnt[tid] = 0;

    // ---- phase 1: X fp32 [64][128], B bf16 [512][72] ----
#pragma unroll
    for (int it = 0; it < 8; it++) {
        int i = tid + it * NTH;
        int d = i >> 5, c = i & 31;
        float4 v = *(const float4*)(xbase + (size_t)d * T_LEN + c * 4);
        *(float4*)(X + d * MT + c * 4) = v;
    }
#pragma unroll
    for (int it = 0; it < 32; it++) {
        int i = tid + it * NTH;                // float4 index over emb
        int n = i >> 4, q = i & 15;
        float4 v = __ldg((const float4*)(emb + n * DIM + q * 4));
        __nv_bfloat162 h0, h1;
        h0.x = __float2bfloat16(v.x); h0.y = __float2bfloat16(v.y);
        h1.x = __float2bfloat16(v.z); h1.y = __float2bfloat16(v.w);
        uint2 pk;
        pk.x = *(uint32_t*)&h0; pk.y = *(uint32_t*)&h1;
        B64[(n * W32 + q * 2) >> 1] = pk;      // word idx even -> uint2 ok
    }
    __syncthreads();

    // ---- phase 2: A bf16 from X, ee exact, xx exact ----
    {
        int m = tid >> 1, db = (tid & 1) * 32;
#pragma unroll
        for (int j = 0; j < 16; j++) {
            int d0 = db + j * 2;
            __nv_bfloat162 h;
            h.x = __float2bfloat16(X[(d0 + 0) * MT + m]);
            h.y = __float2bfloat16(X[(d0 + 1) * MT + m]);
            A2[(m * BP + d0) >> 1] = h;
        }
    }
#pragma unroll
    for (int r = 0; r < 2; r++) {              // ee: sequential chain (exact)
        int k = tid + r * NTH;
        const float* er = emb + k * DIM;
        float s = 0.f;
#pragma unroll
        for (int d = 0; d < DIM; d++) s = fmaf(__ldg(er + d), __ldg(er + d), s);
        see[k] = s;
    }
    if (tid < MT) {                            // |x|^2: sequential chain (exact)
        float s = 0.f;
#pragma unroll
        for (int d = 0; d < DIM; d++) {
            float v = X[d * MT + tid];
            s = fmaf(v, v, s);
        }
        xxs[tid] = s;
    }
    __syncthreads();

    // ---- mainloop: bf16 mma filter over all 512 codes ----
    {
        const int wrow = wid * 16;
        const int qr = lane >> 2;              // quad row
        const int qc = lane & 3;               // quad col
        const int rr0 = wrow + qr, rr1 = rr0 + 8;
        const uint32_t* A32 = (const uint32_t*)(smem + SM_A);
        const uint32_t* B32 = (const uint32_t*)(smem + SM_B);

        uint32_t af[4][4];
#pragma unroll
        for (int ks = 0; ks < 4; ks++) {
            int p0 = (wrow + qr) * W32 + ks * 8 + qc;
            int p1 = (wrow + qr + 8) * W32 + ks * 8 + qc;
            af[ks][0] = A32[p0];
            af[ks][1] = A32[p1];
            af[ks][2] = A32[p0 + 4];
            af[ks][3] = A32[p1 + 4];
        }

        float best0 = 3.4e38f, best1 = 3.4e38f;

#pragma unroll 2
        for (int nt = 0; nt < 64; nt++) {
            const int n0 = nt * 8;
            float d0 = 0.f, d1 = 0.f, d2 = 0.f, d3 = 0.f;
#pragma unroll
            for (int ks = 0; ks < 4; ks++) {
                uint32_t b0 = B32[(n0 + qr) * W32 + ks * 8 + qc];
                uint32_t b1 = B32[(n0 + qr) * W32 + ks * 8 + 4 + qc];
                mma16816(d0, d1, d2, d3,
                         af[ks][0], af[ks][1], af[ks][2], af[ks][3], b0, b1);
            }
            const int cc = n0 + qc * 2;
            float e0 = see[cc], e1 = see[cc + 1];
            float s00 = fmaf(-2.f, d0, e0);
            float s01 = fmaf(-2.f, d1, e1);
            float s10 = fmaf(-2.f, d2, e0);
            float s11 = fmaf(-2.f, d3, e1);

            float t0 = fminf(s00, s01), t1 = fminf(s10, s11);
            t0 = fminf(t0, __shfl_xor_sync(0xffffffffu, t0, 1));
            t0 = fminf(t0, __shfl_xor_sync(0xffffffffu, t0, 2));
            t1 = fminf(t1, __shfl_xor_sync(0xffffffffu, t1, 1));
            t1 = fminf(t1, __shfl_xor_sync(0xffffffffu, t1, 2));
            best0 = fminf(best0, t0);
            best1 = fminf(best1, t1);

            if (s00 < best0 + CAND_W) {
                int sl = atomicAdd(&scnt[rr0], 1);
                if (sl < CAP) scand[rr0 * CAP + sl] = (uint16_t)cc;
            }
            if (s01 < best0 + CAND_W) {
                int sl = atomicAdd(&scnt[rr0], 1);
                if (sl < CAP) scand[rr0 * CAP + sl] = (uint16_t)(cc + 1);
            }
            if (s10 < best1 + CAND_W) {
                int sl = atomicAdd(&scnt[rr1], 1);
                if (sl < CAP) scand[rr1 * CAP + sl] = (uint16_t)cc;
            }
            if (s11 < best1 + CAND_W) {
                int sl = atomicAdd(&scnt[rr1], 1);
                if (sl < CAP) scand[rr1 * CAP + sl] = (uint16_t)(cc + 1);
            }
        }
    }
    __syncthreads();

    // ---- exact refine: bit-identical R2 chain on candidates ----
    if (tid < MT) {
        const int m = tid;
        const int cnt = scnt[m];
        const float xx = xxs[m];
        float bv = 3.4e38f;
        int bk = 0x7fffffff;
        if (cnt <= CAP) {
            for (int i = 0; i < cnt; i++) {
                int k = scand[m * CAP + i];
                const float* er = emb + k * DIM;
                float s = 0.f;
#pragma unroll
                for (int d = 0; d < DIM; d++) s = fmaf(X[d * MT + m], __ldg(er + d), s);
                float dist = fmaf(-2.f, s, xx) + see[k];
                if (dist < bv || (dist == bv && k < bk)) { bv = dist; bk = k; }
            }
        } else {                               // overflow: exact full scan
            for (int k = 0; k < NUM_K; k++) {
                const float* er = emb + k * DIM;
                float s = 0.f;
#pragma unroll
                for (int d = 0; d < DIM; d++) s = fmaf(X[d * MT + m], __ldg(er + d), s);
                float dist = fmaf(-2.f, s, xx) + see[k];
                if (dist < bv) { bv = dist; bk = k; }
            }
        }
        sidx[m] = bk;
        out[IDX_OFF + (size_t)b * T_LEN + t0 + m] = (float)bk;
    }
    __syncthreads();

    // ---- quantized write + loss partial ----
    float* qbase = out + (size_t)b * DIM * T_LEN + t0;
    float lacc = 0.f;
#pragma unroll
    for (int it = 0; it < 8; it++) {
        int i = tid + it * NTH;
        int d = i >> 5, c = i & 31;
        int m0 = c * 4;
        int i0 = sidx[m0], i1 = sidx[m0 + 1], i2 = sidx[m0 + 2], i3 = sidx[m0 + 3];
        float4 q;
        q.x = __ldg(emb + i0 * DIM + d);
        q.y = __ldg(emb + i1 * DIM + d);
        q.z = __ldg(emb + i2 * DIM + d);
        q.w = __ldg(emb + i3 * DIM + d);
        *(float4*)(qbase + (size_t)d * T_LEN + m0) = q;
        const float* xr = X + d * MT;
        float dx;
        dx = q.x - xr[m0 + 0]; lacc = fmaf(dx, dx, lacc);
        dx = q.y - xr[m0 + 1]; lacc = fmaf(dx, dx, lacc);
        dx = q.z - xr[m0 + 2]; lacc = fmaf(dx, dx, lacc);
        dx = q.w - xr[m0 + 3]; lacc = fmaf(dx, dx, lacc);
    }
#pragma unroll
    for (int off = 16; off; off >>= 1)
        lacc += __shfl_xor_sync(0xffffffffu, lacc, off);
    if (lane == 0) redw[wid] = lacc;
    __syncthreads();
    if (tid == 0) {
        double s = 0.0;
#pragma unroll
        for (int w = 0; w < 8; w++) s += (double)redw[w];
        g_partial[blockIdx.x] = s;
    }
}

// ---------------------------------------------------------------------------
__global__ void vq_loss(float* __restrict__ out) {
    int lane = threadIdx.x;                    // 32 threads
    double s = 0.0;
    for (int i = 0; i < NCTA / 32; i++)
        s += g_partial[lane * (NCTA / 32) + i];
#pragma unroll
    for (int off = 16; off; off >>= 1)
        s += __shfl_xor_sync(0xffffffffu, s, off);
    if (lane == 0)
        out[LOSS_OFF] = (float)(s * (1.25 / (double)((size_t)B_LEN * DIM * T_LEN)));
}

// ---------------------------------------------------------------------------
extern "C" void kernel_launch(void* const* d_in, const int* in_sizes, int n_in,
                              void* d_out, int out_size) {
    const float* inp = (const float*)d_in[0];  // [32, 64, 8192] f32
    const float* emb = (const float*)d_in[1];  // [512, 64] f32
    float* out = (float*)d_out;

    cudaFuncSetAttribute(vq_main, cudaFuncAttributeMaxDynamicSharedMemorySize,
                         SMEM_BYTES);
    vq_main<<<NCTA, NTH, SMEM_BYTES>>>(inp, emb, out);
    vq_loss<<<1, 32>>>(out);
}

// round 7
// speedup vs baseline: 3.7618x; 3.7618x over previous
#include <cuda_runtime.h>
#include <cuda_bf16.h>
#include <cstdint>
#include <cstddef>

// ---------------- problem constants ----------------
#define NUM_K 512
#define DIM   64
#define T_LEN 8192
#define B_LEN 32

#define MT    128                      // vectors per CTA
#define NTH   256
#define NCTA  ((B_LEN * T_LEN) / MT)   // 2048
#define CAND_W 6.0e-3f                 // capture window vs TRUE approx min (2eps~2.7e-3)
#define CAP    16                      // candidate queue per row

// bf16 tiles padded to 72 halfs/row (36 words: +4-bank stagger per row
// -> conflict-free quad-fragment LDS)
#define BP 72
#define W32 36

// Output layout: [quantized B*D*T][loss 1][indices as float B*T]
#define LOSS_OFF ((size_t)B_LEN * DIM * T_LEN)
#define IDX_OFF  (LOSS_OFF + 1)

// ---------------- smem layout (bytes) ----------------
#define SM_X     0                     // fp32 [64][128]                32768
#define SM_A     32768                 // bf16 [128][72]                18432
#define SM_B     51200                 // bf16 [512][72]                73728
#define SM_SEE   124928                // fp32 [512]                     2048
#define SM_XXS   126976                // fp32 [128]                      512
#define SM_SIDX  127488                // int  [128]                      512
#define SM_CAND  128000                // u16  [128][CAP]                4096
#define SM_CNT   132096                // int  [128]                      512
#define SM_RV    132608                // fp32 [2][128]                  1024
#define SM_RK    133632                // int  [2][128]                  1024
#define SM_REDW  134656                // fp32 [8]                         32
#define SMEM_BYTES 134688

__device__ double g_partial[NCTA];

__device__ __forceinline__ void mma16816(float& d0, float& d1, float& d2, float& d3,
                                         uint32_t a0, uint32_t a1, uint32_t a2,
                                         uint32_t a3, uint32_t b0, uint32_t b1) {
    asm volatile(
        "mma.sync.aligned.m16n8k16.row.col.f32.bf16.bf16.f32 "
        "{%0,%1,%2,%3}, {%4,%5,%6,%7}, {%8,%9}, {%0,%1,%2,%3};"
        : "+f"(d0), "+f"(d1), "+f"(d2), "+f"(d3)
        : "r"(a0), "r"(a1), "r"(a2), "r"(a3), "r"(b0), "r"(b1));
}

// ---------------------------------------------------------------------------
__global__ void __launch_bounds__(NTH, 1)
vq_main(const float* __restrict__ inp, const float* __restrict__ emb,
        float* __restrict__ out) {
    extern __shared__ char smem[];
    float*     X     = (float*)(smem + SM_X);
    float*     see   = (float*)(smem + SM_SEE);
    float*     xxs   = (float*)(smem + SM_XXS);
    int*       sidx  = (int*)(smem + SM_SIDX);
    uint16_t*  scand = (uint16_t*)(smem + SM_CAND);
    int*       scnt  = (int*)(smem + SM_CNT);
    float*     rv    = (float*)(smem + SM_RV);
    int*       rk    = (int*)(smem + SM_RK);
    float*     redw  = (float*)(smem + SM_REDW);
    __nv_bfloat162* A2 = (__nv_bfloat162*)(smem + SM_A);
    uint2*     B64   = (uint2*)(smem + SM_B);

    const int tid  = threadIdx.x;
    const int wid  = tid >> 5;
    const int lane = tid & 31;

    const int b  = blockIdx.x >> 6;            // 64 tiles of 128 per batch
    const int t0 = (blockIdx.x & 63) * MT;
    const float* xbase = inp + (size_t)b * DIM * T_LEN + t0;

    if (tid < MT) scnt[tid] = 0;

    // ---- phase 1: X fp32 [64][128], B bf16 [512][72] ----
#pragma unroll
    for (int it = 0; it < 8; it++) {
        int i = tid + it * NTH;
        int d = i >> 5, c = i & 31;
        float4 v = *(const float4*)(xbase + (size_t)d * T_LEN + c * 4);
        *(float4*)(X + d * MT + c * 4) = v;
    }
#pragma unroll
    for (int it = 0; it < 32; it++) {
        int i = tid + it * NTH;                // float4 index over emb
        int n = i >> 4, q = i & 15;
        float4 v = __ldg((const float4*)(emb + n * DIM + q * 4));
        __nv_bfloat162 h0, h1;
        h0.x = __float2bfloat16(v.x); h0.y = __float2bfloat16(v.y);
        h1.x = __float2bfloat16(v.z); h1.y = __float2bfloat16(v.w);
        uint2 pk;
        pk.x = *(uint32_t*)&h0; pk.y = *(uint32_t*)&h1;
        B64[(n * W32 + q * 2) >> 1] = pk;      // word idx even -> uint2 ok
    }
    __syncthreads();

    // ---- phase 2: A bf16 from X, ee exact, xx exact ----
    {
        int m = tid >> 1, db = (tid & 1) * 32;
#pragma unroll
        for (int j = 0; j < 16; j++) {
            int d0 = db + j * 2;
            __nv_bfloat162 h;
            h.x = __float2bfloat16(X[(d0 + 0) * MT + m]);
            h.y = __float2bfloat16(X[(d0 + 1) * MT + m]);
            A2[(m * BP + d0) >> 1] = h;
        }
    }
#pragma unroll
    for (int r = 0; r < 2; r++) {              // ee: sequential chain (exact)
        int k = tid + r * NTH;
        const float* er = emb + k * DIM;
        float s = 0.f;
#pragma unroll
        for (int d = 0; d < DIM; d++) s = fmaf(__ldg(er + d), __ldg(er + d), s);
        see[k] = s;
    }
    if (tid < MT) {                            // |x|^2: sequential chain (exact)
        float s = 0.f;
#pragma unroll
        for (int d = 0; d < DIM; d++) {
            float v = X[d * MT + tid];
            s = fmaf(v, v, s);
        }
        xxs[tid] = s;
    }
    __syncthreads();

    // ---- filter: two-pass bf16 mma over all 512 codes ----
    {
        const int wrow = wid * 16;
        const int qr = lane >> 2;              // quad row
        const int qc = lane & 3;               // quad col
        const int rr0 = wrow + qr, rr1 = rr0 + 8;
        const uint32_t* A32 = (const uint32_t*)(smem + SM_A);
        const uint32_t* B32 = (const uint32_t*)(smem + SM_B);

        uint32_t af[4][4];
#pragma unroll
        for (int ks = 0; ks < 4; ks++) {
            int p0 = (wrow + qr) * W32 + ks * 8 + qc;
            int p1 = (wrow + qr + 8) * W32 + ks * 8 + qc;
            af[ks][0] = A32[p0];
            af[ks][1] = A32[p1];
            af[ks][2] = A32[p0 + 4];
            af[ks][3] = A32[p1 + 4];
        }

        // ---- pass 1: row minima only (no pushes, no atomics) ----
        float best0 = 3.4e38f, best1 = 3.4e38f;
#pragma unroll 4
        for (int nt = 0; nt < 64; nt++) {
            const int n0 = nt * 8;
            float d0 = 0.f, d1 = 0.f, d2 = 0.f, d3 = 0.f;
#pragma unroll
            for (int ks = 0; ks < 4; ks++) {
                uint32_t b0 = B32[(n0 + qr) * W32 + ks * 8 + qc];
                uint32_t b1 = B32[(n0 + qr) * W32 + ks * 8 + 4 + qc];
                mma16816(d0, d1, d2, d3,
                         af[ks][0], af[ks][1], af[ks][2], af[ks][3], b0, b1);
            }
            const int cc = n0 + qc * 2;
            float e0 = see[cc], e1 = see[cc + 1];
            best0 = fminf(best0, fminf(fmaf(-2.f, d0, e0), fmaf(-2.f, d1, e1)));
            best1 = fminf(best1, fminf(fmaf(-2.f, d2, e0), fmaf(-2.f, d3, e1)));
        }
        best0 = fminf(best0, __shfl_xor_sync(0xffffffffu, best0, 1));
        best0 = fminf(best0, __shfl_xor_sync(0xffffffffu, best0, 2));
        best1 = fminf(best1, __shfl_xor_sync(0xffffffffu, best1, 1));
        best1 = fminf(best1, __shfl_xor_sync(0xffffffffu, best1, 2));
        const float th0 = best0 + CAND_W;
        const float th1 = best1 + CAND_W;

        // ---- pass 2: re-MMA, push codes within window of TRUE min ----
#pragma unroll 2
        for (int nt = 0; nt < 64; nt++) {
            const int n0 = nt * 8;
            float d0 = 0.f, d1 = 0.f, d2 = 0.f, d3 = 0.f;
#pragma unroll
            for (int ks = 0; ks < 4; ks++) {
                uint32_t b0 = B32[(n0 + qr) * W32 + ks * 8 + qc];
                uint32_t b1 = B32[(n0 + qr) * W32 + ks * 8 + 4 + qc];
                mma16816(d0, d1, d2, d3,
                         af[ks][0], af[ks][1], af[ks][2], af[ks][3], b0, b1);
            }
            const int cc = n0 + qc * 2;
            float e0 = see[cc], e1 = see[cc + 1];
            float s00 = fmaf(-2.f, d0, e0);
            float s01 = fmaf(-2.f, d1, e1);
            float s10 = fmaf(-2.f, d2, e0);
            float s11 = fmaf(-2.f, d3, e1);
            if (s00 < th0) {
                int sl = atomicAdd(&scnt[rr0], 1);
                if (sl < CAP) scand[rr0 * CAP + sl] = (uint16_t)cc;
            }
            if (s01 < th0) {
                int sl = atomicAdd(&scnt[rr0], 1);
                if (sl < CAP) scand[rr0 * CAP + sl] = (uint16_t)(cc + 1);
            }
            if (s10 < th1) {
                int sl = atomicAdd(&scnt[rr1], 1);
                if (sl < CAP) scand[rr1 * CAP + sl] = (uint16_t)cc;
            }
            if (s11 < th1) {
                int sl = atomicAdd(&scnt[rr1], 1);
                if (sl < CAP) scand[rr1 * CAP + sl] = (uint16_t)(cc + 1);
            }
        }
    }
    __syncthreads();

    // ---- exact refine: bit-identical R2 chain, 2 threads per row ----
    {
        const int m    = tid & 127;
        const int part = tid >> 7;             // even/odd candidate split
        const int cnt  = scnt[m];
        const float xx = xxs[m];
        float bv = 3.4e38f;
        int bk = 0x7fffffff;
        if (cnt <= CAP) {
            for (int i = part; i < cnt; i += 2) {
                int k = scand[m * CAP + i];
                const float* er = emb + k * DIM;
                float s = 0.f;
#pragma unroll
                for (int d = 0; d < DIM; d++) s = fmaf(X[d * MT + m], __ldg(er + d), s);
                float dist = fmaf(-2.f, s, xx) + see[k];
                if (dist < bv || (dist == bv && k < bk)) { bv = dist; bk = k; }
            }
        } else if (part == 0) {                // ~never: exact full scan
            for (int k = 0; k < NUM_K; k++) {
                const float* er = emb + k * DIM;
                float s = 0.f;
#pragma unroll
                for (int d = 0; d < DIM; d++) s = fmaf(X[d * MT + m], __ldg(er + d), s);
                float dist = fmaf(-2.f, s, xx) + see[k];
                if (dist < bv) { bv = dist; bk = k; }
            }
        }
        rv[part * MT + m] = bv;
        rk[part * MT + m] = bk;
    }
    __syncthreads();
    if (tid < MT) {
        float v0 = rv[tid], v1 = rv[MT + tid];
        int   k0 = rk[tid], k1 = rk[MT + tid];
        int bi;
        if (v1 < v0 || (v1 == v0 && k1 < k0)) bi = k1; else bi = k0;
        sidx[tid] = bi;
        out[IDX_OFF + (size_t)b * T_LEN + t0 + tid] = (float)bi;
    }
    __syncthreads();

    // ---- quantized write + loss partial ----
    float* qbase = out + (size_t)b * DIM * T_LEN + t0;
    float lacc = 0.f;
#pragma unroll
    for (int it = 0; it < 8; it++) {
        int i = tid + it * NTH;
        int d = i >> 5, c = i & 31;
        int m0 = c * 4;
        int i0 = sidx[m0], i1 = sidx[m0 + 1], i2 = sidx[m0 + 2], i3 = sidx[m0 + 3];
        float4 q;
        q.x = __ldg(emb + i0 * DIM + d);
        q.y = __ldg(emb + i1 * DIM + d);
        q.z = __ldg(emb + i2 * DIM + d);
        q.w = __ldg(emb + i3 * DIM + d);
        *(float4*)(qbase + (size_t)d * T_LEN + m0) = q;
        const float* xr = X + d * MT;
        float dx;
        dx = q.x - xr[m0 + 0]; lacc = fmaf(dx, dx, lacc);
        dx = q.y - xr[m0 + 1]; lacc = fmaf(dx, dx, lacc);
        dx = q.z - xr[m0 + 2]; lacc = fmaf(dx, dx, lacc);
        dx = q.w - xr[m0 + 3]; lacc = fmaf(dx, dx, lacc);
    }
#pragma unroll
    for (int off = 16; off; off >>= 1)
        lacc += __shfl_xor_sync(0xffffffffu, lacc, off);
    if (lane == 0) redw[wid] = lacc;
    __syncthreads();
    if (tid == 0) {
        double s = 0.0;
#pragma unroll
        for (int w = 0; w < 8; w++) s += (double)redw[w];
        g_partial[blockIdx.x] = s;
    }
}

// ---------------------------------------------------------------------------
__global__ void vq_loss(float* __restrict__ out) {
    int lane = threadIdx.x;                    // 32 threads
    double s = 0.0;
    for (int i = 0; i < NCTA / 32; i++)
        s += g_partial[lane * (NCTA / 32) + i];
#pragma unroll
    for (int off = 16; off; off >>= 1)
        s += __shfl_xor_sync(0xffffffffu, s, off);
    if (lane == 0)
        out[LOSS_OFF] = (float)(s * (1.25 / (double)((size_t)B_LEN * DIM * T_LEN)));
}

// ---------------------------------------------------------------------------
extern "C" void kernel_launch(void* const* d_in, const int* in_sizes, int n_in,
                              void* d_out, int out_size) {
    const float* inp = (const float*)d_in[0];  // [32, 64, 8192] f32
    const float* emb = (const float*)d_in[1];  // [512, 64] f32
    float* out = (float*)d_out;

    cudaFuncSetAttribute(vq_main, cudaFuncAttributeMaxDynamicSharedMemorySize,
                         SMEM_BYTES);
    vq_main<<<NCTA, NTH, SMEM_BYTES>>>(inp, emb, out);
    vq_loss<<<1, 32>>>(out);
}

// round 8
// speedup vs baseline: 5.9087x; 1.5707x over previous
#include <cuda_runtime.h>
#include <cuda_bf16.h>
#include <cstdint>
#include <cstddef>

// ---------------- problem constants ----------------
#define NUM_K 512
#define DIM   64
#define T_LEN 8192
#define B_LEN 32

#define MT    128                      // vectors per CTA
#define NTH   256
#define NCTA  ((B_LEN * T_LEN) / MT)   // 2048
#define CAND_W 4.0e-3f                 // capture window (worst-case 2eps = 8.6e-4)
#define CAP    16                      // per-row candidate cap
#define TOTCAP 280                     // CTA-wide staged-candidate slots

// Tile row pitch: 36 words (32 data + 4 pad) -> +4-bank stagger per row
#define W32 36

// Output layout: [quantized B*D*T][loss 1][indices as float B*T]
#define LOSS_OFF ((size_t)B_LEN * DIM * T_LEN)
#define IDX_OFF  (LOSS_OFF + 1)

// ---------------- smem layout (bytes) ----------------
#define SM_X     0                     // fp32 [64][128]                 32768
#define SM_A     32768                 // bf16 [128][36w] interleaved    18432
#define SM_B     51200                 // bf16 [512][36w] interleaved    73728
#define SM_CSTG  51200                 // alias after pass2: fp32[280][65]=72800
#define SM_SEE   124928                // fp32 [512]                      2048
#define SM_XXS   126976                // fp32 [128]                       512
#define SM_SIDX  127488                // int  [128]                       512
#define SM_CAND  128000                // u16  [128][CAP]  (code k)       4096
#define SM_CSLOT 132096                // u16  [128][CAP]  (slot)         4096
#define SM_CNT   136192                // int  [128]                       512
#define SM_SLOTK 136704                // u16  [TOTCAP] (+pad)             576
#define SM_GSLOT 137280                // int (+pad)                        64
#define SM_RV    137344                // fp32 [2][128]                   1024
#define SM_RK    138368                // int  [2][128]                   1024
#define SM_RWS   139392                // int  [2][128]                   1024
#define SM_REDW  140416                // fp32 [8]                          32
#define SM_WSL   140448                // int  [128]                       512
#define SMEM_BYTES 140960

__device__ double   g_partial[NCTA];
__device__ float    g_ee[NUM_K];
__device__ uint32_t g_bpack[NUM_K * W32];   // bf16x2 words, interleaved layout

// interleaved word index for even k: pair (k, k+1)
__host__ __device__ __forceinline__ int kword(int k) {
    return ((k >> 4) << 3) + (k & 6) + ((k >> 3) & 1);
}

__device__ __forceinline__ void mma16816(float& d0, float& d1, float& d2, float& d3,
                                         uint32_t a0, uint32_t a1, uint32_t a2,
                                         uint32_t a3, uint32_t b0, uint32_t b1) {
    asm volatile(
        "mma.sync.aligned.m16n8k16.row.col.f32.bf16.bf16.f32 "
        "{%0,%1,%2,%3}, {%4,%5,%6,%7}, {%8,%9}, {%0,%1,%2,%3};"
        : "+f"(d0), "+f"(d1), "+f"(d2), "+f"(d3)
        : "r"(a0), "r"(a1), "r"(a2), "r"(a3), "r"(b0), "r"(b1));
}

// ---------------------------------------------------------------------------
// Prep: exact ee (sequential chain) + bf16 interleaved pack of emb.
// 8 blocks x 256 threads; block handles 64 codes.
// ---------------------------------------------------------------------------
__global__ void vq_prep(const float* __restrict__ emb) {
    __shared__ float es[64][65];
    const int tid = threadIdx.x;
    const int kb  = blockIdx.x * 64;

    // coalesced stage: 64 rows x 64 floats
#pragma unroll
    for (int it = 0; it < 4; it++) {
        int i = tid + it * 256;                 // float4 index
        int r = i >> 4, q = i & 15;
        float4 v = *(const float4*)(emb + (kb + r) * DIM + q * 4);
        es[r][q * 4 + 0] = v.x; es[r][q * 4 + 1] = v.y;
        es[r][q * 4 + 2] = v.z; es[r][q * 4 + 3] = v.w;
    }
    __syncthreads();

    if (tid < 64) {                             // exact sequential chain
        float s = 0.f;
#pragma unroll
        for (int d = 0; d < DIM; d++) s = fmaf(es[tid][d], es[tid][d], s);
        g_ee[kb + tid] = s;
    }
    // pack: 64 rows x 36 words
#pragma unroll
    for (int it = 0; it < 9; it++) {
        int i = tid + it * 256;
        int r = i / W32, w = i % W32;
        uint32_t val = 0;
        if (w < 32) {
            int ks = w >> 3, j = w & 7;
            int k0 = 16 * ks + 8 * (j & 1) + 2 * (j >> 1);
            __nv_bfloat162 h;
            h.x = __float2bfloat16(es[r][k0]);
            h.y = __float2bfloat16(es[r][k0 + 1]);
            val = *(uint32_t*)&h;
        }
        g_bpack[(kb + r) * W32 + w] = val;
    }
}

// ---------------------------------------------------------------------------
__global__ void __launch_bounds__(NTH, 1)
vq_main(const float* __restrict__ inp, const float* __restrict__ emb,
        float* __restrict__ out) {
    extern __shared__ char smem[];
    float*     X      = (float*)(smem + SM_X);
    float*     CSTG   = (float*)(smem + SM_CSTG);
    float*     see    = (float*)(smem + SM_SEE);
    float*     xxs    = (float*)(smem + SM_XXS);
    int*       sidx   = (int*)(smem + SM_SIDX);
    uint16_t*  scand  = (uint16_t*)(smem + SM_CAND);
    uint16_t*  cslot  = (uint16_t*)(smem + SM_CSLOT);
    int*       scnt   = (int*)(smem + SM_CNT);
    uint16_t*  slotk  = (uint16_t*)(smem + SM_SLOTK);
    int*       gslot  = (int*)(smem + SM_GSLOT);
    float*     rv     = (float*)(smem + SM_RV);
    int*       rk     = (int*)(smem + SM_RK);
    int*       rws    = (int*)(smem + SM_RWS);
    float*     redw   = (float*)(smem + SM_REDW);
    int*       wsl    = (int*)(smem + SM_WSL);
    uint32_t*  A32    = (uint32_t*)(smem + SM_A);
    uint32_t*  B32    = (uint32_t*)(smem + SM_B);

    const int tid  = threadIdx.x;
    const int wid  = tid >> 5;
    const int lane = tid & 31;

    const int b  = blockIdx.x >> 6;            // 64 tiles of 128 per batch
    const int t0 = (blockIdx.x & 63) * MT;
    const float* xbase = inp + (size_t)b * DIM * T_LEN + t0;

    if (tid < MT) scnt[tid] = 0;
    if (tid == 0) *gslot = 0;

    // ---- fills: X fp32 (coalesced), B (linear copy of g_bpack), see ----
#pragma unroll
    for (int it = 0; it < 8; it++) {
        int i = tid + it * NTH;
        int d = i >> 5, c = i & 31;
        float4 v = *(const float4*)(xbase + (size_t)d * T_LEN + c * 4);
        *(float4*)(X + d * MT + c * 4) = v;
    }
#pragma unroll
    for (int it = 0; it < 18; it++) {          // 4608 uint4
        int i = tid + it * NTH;
        ((uint4*)B32)[i] = ((const uint4*)g_bpack)[i];
    }
#pragma unroll
    for (int it = 0; it < 2; it++) {
        int k = tid + it * NTH;
        see[k] = g_ee[k];
    }
    __syncthreads();

    // ---- A bf16 interleaved from X; xx exact ----
    {
        int m = tid >> 1, kb = (tid & 1) * 32;
#pragma unroll
        for (int j = 0; j < 16; j++) {
            int k0 = kb + j * 2;
            __nv_bfloat162 h;
            h.x = __float2bfloat16(X[(k0 + 0) * MT + m]);
            h.y = __float2bfloat16(X[(k0 + 1) * MT + m]);
            A32[m * W32 + kword(k0)] = *(uint32_t*)&h;
        }
    }
    if (tid < MT) {
        float s = 0.f;
#pragma unroll
        for (int d = 0; d < DIM; d++) {
            float v = X[d * MT + tid];
            s = fmaf(v, v, s);
        }
        xxs[tid] = s;
    }
    __syncthreads();

    // ---- filter: two-pass bf16 mma over all 512 codes ----
    {
        const int wrow = wid * 16;
        const int qr = lane >> 2;
        const int qc = lane & 3;
        const int rr0 = wrow + qr, rr1 = rr0 + 8;

        uint32_t af[4][4];
#pragma unroll
        for (int ks = 0; ks < 4; ks++) {
            uint2 lo = *(uint2*)(A32 + (wrow + qr)     * W32 + ks * 8 + 2 * qc);
            uint2 hi = *(uint2*)(A32 + (wrow + qr + 8) * W32 + ks * 8 + 2 * qc);
            af[ks][0] = lo.x; af[ks][2] = lo.y;      // (a0, a2)
            af[ks][1] = hi.x; af[ks][3] = hi.y;      // (a1, a3)
        }

        // ---- pass 1: row minima only ----
        float best0 = 3.4e38f, best1 = 3.4e38f;
#pragma unroll 4
        for (int nt = 0; nt < 64; nt++) {
            const int n0 = nt * 8;
            float d0 = 0.f, d1 = 0.f, d2 = 0.f, d3 = 0.f;
#pragma unroll
            for (int ks = 0; ks < 4; ks++) {
                uint2 bb = *(uint2*)(B32 + (n0 + qr) * W32 + ks * 8 + 2 * qc);
                mma16816(d0, d1, d2, d3,
                         af[ks][0], af[ks][1], af[ks][2], af[ks][3], bb.x, bb.y);
            }
            const int cc = n0 + qc * 2;
            float e0 = see[cc], e1 = see[cc + 1];
            best0 = fminf(best0, fminf(fmaf(-2.f, d0, e0), fmaf(-2.f, d1, e1)));
            best1 = fminf(best1, fminf(fmaf(-2.f, d2, e0), fmaf(-2.f, d3, e1)));
        }
        best0 = fminf(best0, __shfl_xor_sync(0xffffffffu, best0, 1));
        best0 = fminf(best0, __shfl_xor_sync(0xffffffffu, best0, 2));
        best1 = fminf(best1, __shfl_xor_sync(0xffffffffu, best1, 1));
        best1 = fminf(best1, __shfl_xor_sync(0xffffffffu, best1, 2));
        const float th0 = best0 + CAND_W;
        const float th1 = best1 + CAND_W;

        // ---- pass 2: re-MMA, push codes within window of TRUE min ----
#pragma unroll 2
        for (int nt = 0; nt < 64; nt++) {
            const int n0 = nt * 8;
            float d0 = 0.f, d1 = 0.f, d2 = 0.f, d3 = 0.f;
#pragma unroll
            for (int ks = 0; ks < 4; ks++) {
                uint2 bb = *(uint2*)(B32 + (n0 + qr) * W32 + ks * 8 + 2 * qc);
                mma16816(d0, d1, d2, d3,
                         af[ks][0], af[ks][1], af[ks][2], af[ks][3], bb.x, bb.y);
            }
            const int cc = n0 + qc * 2;
            float e0 = see[cc], e1 = see[cc + 1];
            float s00 = fmaf(-2.f, d0, e0);
            float s01 = fmaf(-2.f, d1, e1);
            float s10 = fmaf(-2.f, d2, e0);
            float s11 = fmaf(-2.f, d3, e1);
#pragma unroll
            for (int v = 0; v < 4; v++) {
                float sv = (v == 0) ? s00 : (v == 1) ? s01 : (v == 2) ? s10 : s11;
                int   rr = (v < 2) ? rr0 : rr1;
                float th = (v < 2) ? th0 : th1;
                int   kk = cc + (v & 1);
                if (sv < th) {
                    int sl = atomicAdd(&scnt[rr], 1);
                    if (sl < CAP) {
                        int slot = atomicAdd(gslot, 1);
                        scand[rr * CAP + sl] = (uint16_t)kk;
                        if (slot < TOTCAP) {
                            cslot[rr * CAP + sl] = (uint16_t)slot;
                            slotk[slot] = (uint16_t)kk;
                        } else {
                            cslot[rr * CAP + sl] = 0xFFFFu;
                        }
                    }
                }
            }
        }
    }
    __syncthreads();

    // ---- stage candidate emb rows coalesced into CSTG (B now dead) ----
    {
        int total = *gslot;
        if (total > TOTCAP) total = TOTCAP;
        for (int s = wid; s < total; s += 8) {
            int k = slotk[s];
            float2 v = __ldg((const float2*)(emb + k * DIM) + lane);
            CSTG[s * 65 + 2 * lane + 0] = v.x;
            CSTG[s * 65 + 2 * lane + 1] = v.y;
        }
    }
    __syncthreads();

    // ---- exact refine (bit-identical chain), 2 threads per row ----
    {
        const int m    = tid & 127;
        const int part = tid >> 7;
        const int cnt  = scnt[m];
        const float xx = xxs[m];
        float bv = 3.4e38f;
        int bk = 0x7fffffff, bs = -1;
        if (cnt <= CAP) {
            for (int i = part; i < cnt; i += 2) {
                int k    = scand[m * CAP + i];
                int slot = cslot[m * CAP + i];
                float s = 0.f;
                if (slot != 0xFFFF) {
                    const float* er = CSTG + slot * 65;
#pragma unroll
                    for (int d = 0; d < DIM; d++)
                        s = fmaf(X[d * MT + m], er[d], s);
                } else {
                    const float* er = emb + k * DIM;
#pragma unroll
                    for (int d = 0; d < DIM; d++)
                        s = fmaf(X[d * MT + m], __ldg(er + d), s);
                    slot = -1;
                }
                float dist = fmaf(-2.f, s, xx) + see[k];
                if (dist < bv || (dist == bv && k < bk)) { bv = dist; bk = k; bs = slot; }
            }
        } else if (part == 0) {                // ~never: exact full scan
            for (int k = 0; k < NUM_K; k++) {
                const float* er = emb + k * DIM;
                float s = 0.f;
#pragma unroll
                for (int d = 0; d < DIM; d++)
                    s = fmaf(X[d * MT + m], __ldg(er + d), s);
                float dist = fmaf(-2.f, s, xx) + see[k];
                if (dist < bv) { bv = dist; bk = k; bs = -1; }
            }
        }
        rv[part * MT + m] = bv;
        rk[part * MT + m] = bk;
        rws[part * MT + m] = bs;
    }
    __syncthreads();
    if (tid < MT) {
        float v0 = rv[tid], v1 = rv[MT + tid];
        int   k0 = rk[tid], k1 = rk[MT + tid];
        int bi, bs;
        if (v1 < v0 || (v1 == v0 && k1 < k0)) { bi = k1; bs = rws[MT + tid]; }
        else                                   { bi = k0; bs = rws[tid]; }
        sidx[tid] = bi;
        wsl[tid]  = bs;
        out[IDX_OFF + (size_t)b * T_LEN + t0 + tid] = (float)bi;
    }
    __syncthreads();

    // ---- quantized write (gather from CSTG) + loss partial ----
    float* qbase = out + (size_t)b * DIM * T_LEN + t0;
    float lacc = 0.f;
#pragma unroll
    for (int it = 0; it < 8; it++) {
        int i = tid + it * NTH;
        int d = i >> 5, c = i & 31;
        int m0 = c * 4;
        float4 q;
#pragma unroll
        for (int z = 0; z < 4; z++) {
            int ws = wsl[m0 + z];
            float val = (ws >= 0) ? CSTG[ws * 65 + d]
                                  : __ldg(emb + sidx[m0 + z] * DIM + d);
            ((float*)&q)[z] = val;
        }
        *(float4*)(qbase + (size_t)d * T_LEN + m0) = q;
        const float* xr = X + d * MT;
        float dx;
        dx = q.x - xr[m0 + 0]; lacc = fmaf(dx, dx, lacc);
        dx = q.y - xr[m0 + 1]; lacc = fmaf(dx, dx, lacc);
        dx = q.z - xr[m0 + 2]; lacc = fmaf(dx, dx, lacc);
        dx = q.w - xr[m0 + 3]; lacc = fmaf(dx, dx, lacc);
    }
#pragma unroll
    for (int off = 16; off; off >>= 1)
        lacc += __shfl_xor_sync(0xffffffffu, lacc, off);
    if (lane == 0) redw[wid] = lacc;
    __syncthreads();
    if (tid == 0) {
        double s = 0.0;
#pragma unroll
        for (int w = 0; w < 8; w++) s += (double)redw[w];
        g_partial[blockIdx.x] = s;
    }
}

// ---------------------------------------------------------------------------
__global__ void vq_loss(float* __restrict__ out) {
    int lane = threadIdx.x;                    // 32 threads
    double s = 0.0;
    for (int i = 0; i < NCTA / 32; i++)
        s += g_partial[lane * (NCTA / 32) + i];
#pragma unroll
    for (int off = 16; off; off >>= 1)
        s += __shfl_xor_sync(0xffffffffu, s, off);
    if (lane == 0)
        out[LOSS_OFF] = (float)(s * (1.25 / (double)((size_t)B_LEN * DIM * T_LEN)));
}

// ---------------------------------------------------------------------------
extern "C" void kernel_launch(void* const* d_in, const int* in_sizes, int n_in,
                              void* d_out, int out_size) {
    const float* inp = (const float*)d_in[0];  // [32, 64, 8192] f32
    const float* emb = (const float*)d_in[1];  // [512, 64] f32
    float* out = (float*)d_out;

    cudaFuncSetAttribute(vq_main, cudaFuncAttributeMaxDynamicSharedMemorySize,
                         SMEM_BYTES);
    vq_prep<<<8, 256>>>(emb);
    vq_main<<<NCTA, NTH, SMEM_BYTES>>>(inp, emb, out);
    vq_loss<<<1, 32>>>(out);
}

// round 10
// speedup vs baseline: 7.3987x; 1.2522x over previous
#include <cuda_runtime.h>
#include <cuda_bf16.h>
#include <cstdint>
#include <cstddef>

// ---------------- problem constants ----------------
#define NUM_K 512
#define DIM   64
#define T_LEN 8192
#define B_LEN 32

#define MT    256
#define NTH   256
#define NCTA  1024                 // (B*T)/MT
#define CAP   16                   // per-row candidate cap
#define WLCAP 4096                 // worklist entries

// Output layout: [quantized B*D*T][loss 1][indices as float B*T]
#define LOSS_OFF ((size_t)B_LEN * DIM * T_LEN)
#define IDX_OFF  (LOSS_OFF + 1)

// ---------------- smem layout (bytes) ----------------
#define SM_X     0                 // fp32 [64][256]                 65536
#define SM_SEE   65536             // fp32 [512]                      2048
#define SM_C     67584             // fp32 [256]  c_m = -2*sx*se      1024
#define SM_W     68608             // fp32 [256]  window W_m          1024
#define SM_XX    69632             // fp32 [256]  |x|^2 exact         1024
#define SM_TH    70656             // fp32 [256]  rowmin+W            1024
#define SM_SCNT  71680             // int  [256]                      1024
#define SM_SCAND 72704             // u16  [256][CAP]                 8192
#define SM_WL    80896             // u16  [WLCAP]                    8192
#define SM_WLC   89088             // int wlcnt, int gflag              64
#define SM_REDW  89152             // fp32 [8]                          64
#define SM_SIDX  89216             // int  [256]                      1024
#define SM_E     90240             // fp32 [512][65] = 133120 (aliased below pre-load)
#define EP_OFF   0                 //   int  [512][16]  e int8 words  32768
#define BM_OFF   32768             //   bf16 [256][66]  block minima  33792
#define X8_OFF   66560             //   int  [16][256]  x int8 words  16384
#define SMEM_BYTES (SM_E + NUM_K * 65 * 4)   // 223360

__device__ double   g_partial[NCTA];
__device__ float    g_ee[NUM_K];
__device__ float    g_se;          // global e quant scale
__device__ float    g_l1e;         // max_k ||e_k||_1
__device__ uint32_t g_epack[NUM_K * 16];

// signed dp4a, explicit int types (avoids overload ambiguity)
__device__ __forceinline__ int dp4a_s8(int a, int b, int c) {
    int r;
    asm("dp4a.s32.s32 %0, %1, %2, %3;" : "=r"(r) : "r"(a), "r"(b), "r"(c));
    return r;
}

// ---------------------------------------------------------------------------
// Prep: exact ee, e-scale, L1 max, int8 pack of emb. One block, 512 threads.
// ---------------------------------------------------------------------------
__global__ void vq_prep(const float* __restrict__ emb) {
    __shared__ float redmx[16], redl1[16], sgmx[1];
    const int k = threadIdx.x;                 // one code per thread
    const int lane = k & 31, wid = k >> 5;

    float ev[DIM];
    float ee = 0.f, l1 = 0.f, mx = 0.f;
#pragma unroll
    for (int d = 0; d < DIM; d++) {
        float e = __ldg(emb + k * DIM + d);
        ev[d] = e;
        ee = fmaf(e, e, ee);                   // exact sequential chain
        float a = fabsf(e);
        l1 += a;
        mx = fmaxf(mx, a);
    }
    g_ee[k] = ee;

#pragma unroll
    for (int off = 16; off; off >>= 1) {
        mx = fmaxf(mx, __shfl_xor_sync(0xffffffffu, mx, off));
        l1 = fmaxf(l1, __shfl_xor_sync(0xffffffffu, l1, off));
    }
    if (lane == 0) { redmx[wid] = mx; redl1[wid] = l1; }
    __syncthreads();
    if (k == 0) {
        float gm = 0.f, gl = 0.f;
        for (int w = 0; w < 16; w++) {
            gm = fmaxf(gm, redmx[w]);
            gl = fmaxf(gl, redl1[w]);
        }
        sgmx[0] = gm;
        g_l1e   = gl;
        g_se    = gm / 127.0f;
    }
    __syncthreads();
    const float gmx = sgmx[0];

    float inv = (gmx > 0.f) ? (127.0f / gmx) : 0.f;
#pragma unroll
    for (int dq = 0; dq < 16; dq++) {
        uint32_t w = 0;
#pragma unroll
        for (int r = 0; r < 4; r++) {
            int q = __float2int_rn(ev[dq * 4 + r] * inv);
            q = max(-127, min(127, q));
            w |= ((uint32_t)q & 0xFFu) << (r * 8);
        }
        g_epack[k * 16 + dq] = w;
    }
}

// ---------------------------------------------------------------------------
__global__ void __launch_bounds__(NTH, 1)
vq_main(const float* __restrict__ inp, const float* __restrict__ emb,
        float* __restrict__ out) {
    extern __shared__ char smem[];
    float*     X     = (float*)(smem + SM_X);
    float*     see   = (float*)(smem + SM_SEE);
    float*     svC   = (float*)(smem + SM_C);
    float*     svW   = (float*)(smem + SM_W);
    float*     svXX  = (float*)(smem + SM_XX);
    float*     svTH  = (float*)(smem + SM_TH);
    int*       scnt  = (int*)(smem + SM_SCNT);
    uint16_t*  scand = (uint16_t*)(smem + SM_SCAND);
    uint16_t*  wl    = (uint16_t*)(smem + SM_WL);
    int*       wlc   = (int*)(smem + SM_WLC);        // [0]=count [1]=gflag
    float*     redw  = (float*)(smem + SM_REDW);
    int*       sidx  = (int*)(smem + SM_SIDX);
    float*     E     = (float*)(smem + SM_E);
    int*       EP    = (int*)(smem + SM_E + EP_OFF);
    uint16_t*  BM    = (uint16_t*)(smem + SM_E + BM_OFF);
    int*       X8    = (int*)(smem + SM_E + X8_OFF);

    const int tid  = threadIdx.x;
    const int wid  = tid >> 5;
    const int lane = tid & 31;

    const int b  = blockIdx.x >> 5;             // 32 tiles of 256 per batch
    const int t0 = (blockIdx.x & 31) * MT;
    const float* xbase = inp + (size_t)b * DIM * T_LEN + t0;

    scnt[tid] = 0;
    if (tid == 0) { wlc[0] = 0; wlc[1] = 0; }

    // ---- fills: X fp32, EP int8 words, see ----
#pragma unroll
    for (int it = 0; it < 16; it++) {
        int i = tid + it * NTH;
        int d = i >> 6, c = i & 63;
        float4 v = *(const float4*)(xbase + (size_t)d * T_LEN + c * 4);
        *(float4*)(X + d * MT + c * 4) = v;
    }
#pragma unroll
    for (int it = 0; it < 8; it++) {            // 2048 uint4
        int i = tid + it * NTH;
        ((uint4*)EP)[i] = ((const uint4*)g_epack)[i];
    }
#pragma unroll
    for (int it = 0; it < 2; it++) see[tid + it * NTH] = g_ee[tid + it * NTH];
    __syncthreads();

    const float se  = g_se;
    const float l1e = g_l1e;

    // ---- per-vector stats + int8 pack (thread m = tid) ----
    {
        const int m = tid;
        float mx = 0.f, xx = 0.f;
#pragma unroll
        for (int d = 0; d < DIM; d++) {
            float v = X[d * MT + m];
            xx = fmaf(v, v, xx);                // exact sequential |x|^2
            mx = fmaxf(mx, fabsf(v));
        }
        float sx  = mx / 127.0f;
        float inv = (mx > 0.f) ? (127.0f / mx) : 0.f;
        int   l1q = 0;
#pragma unroll
        for (int dq = 0; dq < 16; dq++) {
            uint32_t w = 0;
#pragma unroll
            for (int r = 0; r < 4; r++) {
                int q = __float2int_rn(X[(dq * 4 + r) * MT + m] * inv);
                q = max(-127, min(127, q));
                l1q += abs(q);
                w |= ((uint32_t)q & 0xFFu) << (r * 8);
            }
            X8[dq * MT + m] = (int)w;
        }
        svXX[m] = xx;
        svC[m]  = -2.0f * sx * se;
        float Eb = 0.5f * sx * (l1e * 1.0001f + se * (float)l1q);
        svW[m]  = 4.2f * Eb + 5.0e-4f;          // rigorous capture window
    }
    __syncthreads();

    // ---- pass 1: dp4a filter, record per-8-code block minima (bf16-RD) ----
    {
        const int tx = tid & 63;
        const int ty = tid >> 6;
        float c[4];
#pragma unroll
        for (int j = 0; j < 4; j++) c[j] = svC[tx + 64 * j];

        for (int pass = 0; pass < 16; pass++) {
            const int kbase = ty * 128 + pass * 8;
            const int blk   = ty * 16 + pass;
            int acc[4][8];
#pragma unroll
            for (int j = 0; j < 4; j++)
#pragma unroll
                for (int kk = 0; kk < 8; kk++) acc[j][kk] = 0;

#pragma unroll 4
            for (int dq = 0; dq < 16; dq++) {
                int xw[4], ew[8];
#pragma unroll
                for (int j = 0; j < 4; j++) xw[j] = X8[dq * MT + tx + 64 * j];
#pragma unroll
                for (int kk = 0; kk < 8; kk++) ew[kk] = EP[(kbase + kk) * 16 + dq];
#pragma unroll
                for (int j = 0; j < 4; j++)
#pragma unroll
                    for (int kk = 0; kk < 8; kk++)
                        acc[j][kk] = dp4a_s8(xw[j], ew[kk], acc[j][kk]);
            }
            float bmin[4] = {3.4e38f, 3.4e38f, 3.4e38f, 3.4e38f};
#pragma unroll
            for (int kk = 0; kk < 8; kk++) {
                float eek = see[kbase + kk];
#pragma unroll
                for (int j = 0; j < 4; j++) {
                    float s = fmaf(c[j], (float)acc[j][kk], eek);
                    bmin[j] = fminf(bmin[j], s);
                }
            }
#pragma unroll
            for (int j = 0; j < 4; j++) {
                __nv_bfloat16 h = __float2bfloat16_rd(bmin[j]);
                BM[(tx + 64 * j) * 66 + blk] = *(uint16_t*)&h;
            }
        }
    }
    __syncthreads();

    // ---- row thresholds + block worklist (thread m = tid) ----
    {
        const int m = tid;
        float mn = 3.4e38f;
#pragma unroll 8
        for (int bk = 0; bk < 64; bk++) {
            uint32_t u = (uint32_t)BM[m * 66 + bk] << 16;
            mn = fminf(mn, __uint_as_float(u));
        }
        float th = mn + svW[m];
        svTH[m] = th;
#pragma unroll 8
        for (int bk = 0; bk < 64; bk++) {
            uint32_t u = (uint32_t)BM[m * 66 + bk] << 16;
            if (__uint_as_float(u) <= th) {
                int pos = atomicAdd(wlc, 1);
                if (pos < WLCAP) wl[pos] = (uint16_t)((m << 6) | bk);
                else             wlc[1] = 1;
            }
        }
    }
    __syncthreads();

    // ---- pass 2: rescan flagged blocks only (int dot identical) ----
    {
        int n = wlc[0]; if (n > WLCAP) n = WLCAP;
        for (int e = wid; e < n; e += 8) {
            int ent = wl[e];
            int m = ent >> 6, bk = ent & 63;
            int kbase = bk * 8;
            if (lane < 8) {
                int k = kbase + lane;
                int acc = 0;
#pragma unroll
                for (int dq = 0; dq < 16; dq++)
                    acc = dp4a_s8(X8[dq * MT + m], EP[k * 16 + dq], acc);
                float s = fmaf(svC[m], (float)acc, see[k]);
                if (s <= svTH[m]) {
                    int sl = atomicAdd(&scnt[m], 1);
                    if (sl < CAP) scand[m * CAP + sl] = (uint16_t)k;
                }
            }
        }
    }
    __syncthreads();

    // ---- load E fp32 [512][65] (overwrites EP/BM/X8 — now dead) ----
#pragma unroll
    for (int it = 0; it < 32; it++) {
        int i = tid + it * NTH;                 // float4 index
        int k = i >> 4, q = i & 15;
        float4 v = __ldg((const float4*)(emb + k * DIM + q * 4));
        float* row = E + k * 65 + q * 4;
        row[0] = v.x; row[1] = v.y; row[2] = v.z; row[3] = v.w;
    }
    __syncthreads();

    // ---- exact refine (bit-identical R2 chain), thread per row ----
    {
        const int m   = tid;
        const int cnt = scnt[m];
        const float xx = svXX[m];
        float bv = 3.4e38f;
        int   bk = 0x7fffffff;
        if (!wlc[1] && cnt <= CAP) {
            for (int i = 0; i < cnt; i++) {
                int k = scand[m * CAP + i];
                const float* er = E + k * 65;
                float s = 0.f;
#pragma unroll
                for (int d = 0; d < DIM; d++) s = fmaf(X[d * MT + m], er[d], s);
                float dist = fmaf(-2.f, s, xx) + see[k];
                if (dist < bv || (dist == bv && k < bk)) { bv = dist; bk = k; }
            }
        } else {                                // ~never: exact full scan
            for (int k = 0; k < NUM_K; k++) {
                const float* er = E + k * 65;
                float s = 0.f;
#pragma unroll
                for (int d = 0; d < DIM; d++) s = fmaf(X[d * MT + m], er[d], s);
                float dist = fmaf(-2.f, s, xx) + see[k];
                if (dist < bv) { bv = dist; bk = k; }
            }
        }
        sidx[m] = bk;
        out[IDX_OFF + (size_t)b * T_LEN + t0 + m] = (float)bk;
    }
    __syncthreads();

    // ---- quantized write (gather from E smem) + loss partial ----
    float* qbase = out + (size_t)b * DIM * T_LEN + t0;
    float lacc = 0.f;
#pragma unroll
    for (int it = 0; it < 16; it++) {
        int i = tid + it * NTH;
        int d = i >> 6, c = i & 63;
        int m0 = c * 4;
        int i0 = sidx[m0], i1 = sidx[m0 + 1], i2 = sidx[m0 + 2], i3 = sidx[m0 + 3];
        float4 q;
        q.x = E[i0 * 65 + d];
        q.y = E[i1 * 65 + d];
        q.z = E[i2 * 65 + d];
        q.w = E[i3 * 65 + d];
        *(float4*)(qbase + (size_t)d * T_LEN + m0) = q;
        const float* xr = X + d * MT;
        float dx;
        dx = q.x - xr[m0 + 0]; lacc = fmaf(dx, dx, lacc);
        dx = q.y - xr[m0 + 1]; lacc = fmaf(dx, dx, lacc);
        dx = q.z - xr[m0 + 2]; lacc = fmaf(dx, dx, lacc);
        dx = q.w - xr[m0 + 3]; lacc = fmaf(dx, dx, lacc);
    }
#pragma unroll
    for (int off = 16; off; off >>= 1)
        lacc += __shfl_xor_sync(0xffffffffu, lacc, off);
    if (lane == 0) redw[wid] = lacc;
    __syncthreads();
    if (tid == 0) {
        double s = 0.0;
#pragma unroll
        for (int w = 0; w < 8; w++) s += (double)redw[w];
        g_partial[blockIdx.x] = s;
    }
}

// ---------------------------------------------------------------------------
__global__ void vq_loss(float* __restrict__ out) {
    int lane = threadIdx.x;                     // 32 threads
    double s = 0.0;
    for (int i = 0; i < NCTA / 32; i++)
        s += g_partial[lane * (NCTA / 32) + i];
#pragma unroll
    for (int off = 16; off; off >>= 1)
        s += __shfl_xor_sync(0xffffffffu, s, off);
    if (lane == 0)
        out[LOSS_OFF] = (float)(s * (1.25 / (double)((size_t)B_LEN * DIM * T_LEN)));
}

// ---------------------------------------------------------------------------
extern "C" void kernel_launch(void* const* d_in, const int* in_sizes, int n_in,
                              void* d_out, int out_size) {
    const float* inp = (const float*)d_in[0];   // [32, 64, 8192] f32
    const float* emb = (const float*)d_in[1];   // [512, 64] f32
    float* out = (float*)d_out;

    cudaFuncSetAttribute(vq_main, cudaFuncAttributeMaxDynamicSharedMemorySize,
                         SMEM_BYTES);
    vq_prep<<<1, NUM_K>>>(emb);
    vq_main<<<NCTA, NTH, SMEM_BYTES>>>(inp, emb, out);
    vq_loss<<<1, 32>>>(out);
}